// round 4
// baseline (speedup 1.0000x reference)
#include <cuda_runtime.h>

// Advect stencil, 2 rows x 8 outputs per thread, all 12 LDG.128 front-batched
// for maximum per-warp MLP (two independent dependency chains).
// L = 8192 per row, output 8188. 1024 slots/row (slot 1023 emits only 4).

#define ROW_L     8192
#define ROW_OUT   8188
#define SLOTS_ROW 1024
#define THETA     2.0f

__device__ __forceinline__ float minmod3(float a, float b, float c) {
    float mn = fminf(fminf(a, b), c);
    float mx = fmaxf(fmaxf(a, b), c);
    return (mn < 0.0f) ? fminf(mx, 0.0f) : mn;
}

// Compute 8 outputs (2 float4) for window [k0..k0+11] of one row.
__device__ __forceinline__ void compute8(const float4& ra, const float4& rb, const float4& rc,
                                         const float4& va, const float4& vb, const float4& vc,
                                         int k0, float4& o0, float4& o1) {
    float vv[12] = {va.x, va.y, va.z, va.w, vb.x, vb.y, vb.z, vb.w,
                    vc.x, vc.y, vc.z, vc.w};
    float rr[12] = {ra.x, ra.y, ra.z, ra.w, rb.x, rb.y, rb.z, rb.w,
                    rc.x, rc.y, rc.z, rc.w};
    float f[12];
    #pragma unroll
    for (int i = 0; i < 12; i++) f[i] = rr[i] * vv[i];

    float hs[10];
    #pragma unroll
    for (int i = 0; i < 10; i++) {
        float c0 = THETA * (f[i + 1] - f[i]);
        float c1 = 0.5f  * (f[i + 2] - f[i]);
        float c2 = THETA * (f[i + 2] - f[i + 1]);
        hs[i] = 0.5f * minmod3(c0, c1, c2);
    }

    float net[9];
    #pragma unroll
    for (int j = 0; j < 9; j++) {
        int gj = k0 + j;
        float fm = (vv[j + 2] >= 0.0f) ? 0.0f : (f[j + 2] - hs[j + 1]);
        float fp = (vv[j + 1] <= 0.0f) ? 0.0f : (f[j + 1] + hs[j]);
        if (gj == 0)          fp = 0.0f;   // flux_plus[0] = 0
        if (gj == ROW_L - 4)  fm = 0.0f;   // flux_minus[L-4] = 0
        net[j] = fm + fp;
    }

    o0.x = net[0] - net[1];
    o0.y = net[1] - net[2];
    o0.z = net[2] - net[3];
    o0.w = net[3] - net[4];
    o1.x = net[4] - net[5];
    o1.y = net[5] - net[6];
    o1.z = net[6] - net[7];
    o1.w = net[7] - net[8];
}

__global__ __launch_bounds__(256)
void advect_kernel(const float* __restrict__ rho,
                   const float* __restrict__ v,
                   float* __restrict__ out) {
    const int t  = blockIdx.x * blockDim.x + threadIdx.x;   // slot in row, 0..1023
    const int r0 = blockIdx.y * 2;                          // row pair

    const float* rrho0 = rho + (size_t)r0 * ROW_L;
    const float* rv0   = v   + (size_t)r0 * ROW_L;
    float*       rout0 = out + (size_t)r0 * ROW_OUT;
    const float* rrho1 = rrho0 + ROW_L;
    const float* rv1   = rv0   + ROW_L;
    float*       rout1 = rout0 + ROW_OUT;

    const int  k0   = t * 8;
    const bool full = (t != SLOTS_ROW - 1);

    // ---- front-batch all 12 loads (two independent chains) ----
    float4 ra0 = *reinterpret_cast<const float4*>(rrho0 + k0);
    float4 va0 = *reinterpret_cast<const float4*>(rv0   + k0);
    float4 rb0 = *reinterpret_cast<const float4*>(rrho0 + k0 + 4);
    float4 vb0 = *reinterpret_cast<const float4*>(rv0   + k0 + 4);
    float4 ra1 = *reinterpret_cast<const float4*>(rrho1 + k0);
    float4 va1 = *reinterpret_cast<const float4*>(rv1   + k0);
    float4 rb1 = *reinterpret_cast<const float4*>(rrho1 + k0 + 4);
    float4 vb1 = *reinterpret_cast<const float4*>(rv1   + k0 + 4);
    float4 rc0 = make_float4(0.f, 0.f, 0.f, 0.f);
    float4 vc0 = rc0, rc1 = rc0, vc1 = rc0;
    if (full) {
        rc0 = *reinterpret_cast<const float4*>(rrho0 + k0 + 8);
        vc0 = *reinterpret_cast<const float4*>(rv0   + k0 + 8);
        rc1 = *reinterpret_cast<const float4*>(rrho1 + k0 + 8);
        vc1 = *reinterpret_cast<const float4*>(rv1   + k0 + 8);
    }

    // ---- group 0 ----
    float4 o0a, o0b;
    compute8(ra0, rb0, rc0, va0, vb0, vc0, k0, o0a, o0b);
    __stcs(reinterpret_cast<float4*>(rout0 + k0), o0a);
    if (full) __stcs(reinterpret_cast<float4*>(rout0 + k0 + 4), o0b);

    // ---- group 1 ----
    float4 o1a, o1b;
    compute8(ra1, rb1, rc1, va1, vb1, vc1, k0, o1a, o1b);
    __stcs(reinterpret_cast<float4*>(rout1 + k0), o1a);
    if (full) __stcs(reinterpret_cast<float4*>(rout1 + k0 + 4), o1b);
}

extern "C" void kernel_launch(void* const* d_in, const int* in_sizes, int n_in,
                              void* d_out, int out_size) {
    const float* rho = (const float*)d_in[0];
    const float* v   = (const float*)d_in[1];
    float* out = (float*)d_out;

    int rows = in_sizes[0] / ROW_L;   // 16*256 = 4096

    dim3 block(256);
    dim3 grid(SLOTS_ROW / 256, rows / 2);   // (4, 2048)
    advect_kernel<<<grid, block>>>(rho, v, out);
}